// round 9
// baseline (speedup 1.0000x reference)
#include <cuda_runtime.h>
#include <cstdint>

#define BATCH   8
#define CH      256
#define HH      80
#define WW      80
#define HW      (HH*WW)          // 6400
#define HW2     (HW/2)           // 3200 float2 per channel
#define OC      32
#define GROUPS  4
#define OH      160
#define OW      160
#define OHW     (OH*OW)          // 25600

#define SC      16               // channels per conv stage
#define NSTAGE  (CH/SC)          // 16

typedef unsigned long long ull;

// scratch: conv output (6.55 MB) + packed weights (64 KB)
__device__ float g_off[BATCH * OC * HW];
__device__ ull   g_wp[CH * OC];          // [c][o] = (w,w) packed

__device__ __forceinline__ ull pack2(float a, float b) {
    ull r;
    asm("mov.b64 %0, {%1, %2};" : "=l"(r) : "f"(a), "f"(b));
    return r;
}

__device__ __forceinline__ ull ffma2(ull a, ull b, ull c) {
    ull d;
    asm("fma.rn.f32x2 %0, %1, %2, %3;" : "=l"(d) : "l"(a), "l"(b), "l"(c));
    return d;
}

// ---------------------------------------------------------------------------
// Kernel 0: pack weights [o][c] -> [c][o] as (w,w) u64. 8192 items.
// ---------------------------------------------------------------------------
__global__ void pack_w_kernel(const float* __restrict__ wq) {
    int i = blockIdx.x * 256 + threadIdx.x;   // 0..8191
    int c = i >> 5;
    int o = i & 31;
    float w = __ldg(&wq[o * CH + c]);
    g_wp[c * OC + o] = pack2(w, w);
}

// ---------------------------------------------------------------------------
// Kernel 1 (v9): 1x1 conv. 800 blocks x 128 thr (4 warps).
// Warp og covers oc [8*og, 8*og+8); lane = one float2 position.
// Weights: packed u64 from gmem (64KB, L1-resident, uniform-address LDG.128).
// x: smem triple-buffer (read-once from L2), ONE barrier per 16-ch stage.
// Inner body per c: 4 LDG.128(w) + 1 LDS.64(x) + 8 FFMA2 -> 62% fma slots.
// ---------------------------------------------------------------------------
__global__ void __launch_bounds__(128)
conv_off_kernel(const float* __restrict__ x,
                const float* __restrict__ bias) {
    __shared__ ull xs[3][SC][32];        // 3 x 4 KB

    int tid  = threadIdx.x;
    int lane = tid & 31;
    int og   = tid >> 5;                 // 0..3, 8 oc each

    int b  = blockIdx.x / 100;
    int pb = (blockIdx.x % 100) * 32;    // float2 base within channel
    const ull* xb = reinterpret_cast<const ull*>(x) + (size_t)b * CH * HW2 + pb;

    // stage loader mapping: item i = tid + 128k -> cl = (tid>>5)+4k, q = tid&31
    int cl0 = tid >> 5;                  // 0..3
    int q0  = tid & 31;

    // prologue: stage 0 -> buf 0 ; preload stage 1 into regs
    ull r[4];
#pragma unroll
    for (int k = 0; k < 4; k++)
        xs[0][cl0 + 4 * k][q0] = __ldg(xb + (size_t)(cl0 + 4 * k) * HW2 + q0);
#pragma unroll
    for (int k = 0; k < 4; k++)
        r[k] = __ldg(xb + (size_t)(SC + cl0 + 4 * k) * HW2 + q0);
    __syncthreads();

    ull acc[8];
#pragma unroll
    for (int o = 0; o < 8; o++) acc[o] = 0ULL;

#pragma unroll 1
    for (int st = 0; st < NSTAGE; st++) {
        int cb = st * SC;

        // store stage st+1 (in regs) to buffer (st+1)%3 — its previous
        // contents (stage st-2) were last read 2 syncs ago: safe.
        if (st + 1 < NSTAGE) {
            int bufn = (st + 1) % 3;
#pragma unroll
            for (int k = 0; k < 4; k++)
                xs[bufn][cl0 + 4 * k][q0] = r[k];
        }
        // issue gmem loads for stage st+2
        if (st + 2 < NSTAGE) {
#pragma unroll
            for (int k = 0; k < 4; k++)
                r[k] = __ldg(xb + (size_t)(cb + 2 * SC + cl0 + 4 * k) * HW2 + q0);
        }
        __syncthreads();                 // stage st+1 visible; stage st ready

        int buf = st % 3;
        const ulonglong2* wr0 =
            reinterpret_cast<const ulonglong2*>(g_wp + cb * OC + og * 8);
#pragma unroll
        for (int cl = 0; cl < SC; cl++) {
            ull xv = xs[buf][cl][lane];
            const ulonglong2* wr = wr0 + cl * (OC / 2);
            ulonglong2 w01 = __ldg(wr);
            ulonglong2 w23 = __ldg(wr + 1);
            ulonglong2 w45 = __ldg(wr + 2);
            ulonglong2 w67 = __ldg(wr + 3);
            acc[0] = ffma2(xv, w01.x, acc[0]);
            acc[1] = ffma2(xv, w01.y, acc[1]);
            acc[2] = ffma2(xv, w23.x, acc[2]);
            acc[3] = ffma2(xv, w23.y, acc[3]);
            acc[4] = ffma2(xv, w45.x, acc[4]);
            acc[5] = ffma2(xv, w45.y, acc[5]);
            acc[6] = ffma2(xv, w67.x, acc[6]);
            acc[7] = ffma2(xv, w67.y, acc[7]);
        }
    }

    float2* offp = reinterpret_cast<float2*>(g_off) + (size_t)b * OC * HW2 + pb;
#pragma unroll
    for (int o = 0; o < 8; o++) {
        int oc = og * 8 + o;
        float bo = __ldg(&bias[oc]);
        float2 v;
        v.x = __uint_as_float((unsigned)(acc[o] & 0xffffffffULL)) + bo;
        v.y = __uint_as_float((unsigned)(acc[o] >> 32)) + bo;
        offp[(size_t)oc * HW2 + lane] = v;
    }
}

// ---------------------------------------------------------------------------
// Kernel 2 (v7, unchanged): tiled bilinear sampling.
// ---------------------------------------------------------------------------
__device__ __noinline__ void sample_fallback(
    const float* __restrict__ offb, const float* __restrict__ bp,
    float* __restrict__ opb, int gi, int hbase, int wbase, int ohb, int owb)
{
    for (int c = 0; c < 16; c++) {
        const float* pc = bp + (size_t)c * HW;
        float* oc = opb + (size_t)c * OHW;
        for (int r = 0; r < 4; r++) {
            float vv[4];
            for (int s = 0; s < 4; s++) {
                int hprime = hbase + (r >> 1);
                int i = r & 1;
                int wprime = wbase + (s >> 1);
                int j = s & 1;
                int k = gi * 4 + i * 2 + j;
                const float* op2 = offb + hprime * WW + wprime;
                float offx = __ldg(op2 + (size_t)k * HW);
                float offy = __ldg(op2 + (size_t)(16 + k) * HW);
                float px = (float)wprime + 0.25f * (offx + (float)(2 * j - 1));
                float py = (float)hprime + 0.25f * (offy + (float)(2 * i - 1));
                float ix = fminf(fmaxf(px, 0.0f), (float)(WW - 1));
                float iy = fminf(fmaxf(py, 0.0f), (float)(HH - 1));
                float fx = floorf(ix), fy = floorf(iy);
                int x0 = (int)fx, y0 = (int)fy;
                float wx = ix - fx, wy = iy - fy;
                int x1 = min(x0 + 1, WW - 1);
                int y1 = min(y0 + 1, HH - 1);
                float a0 = __ldg(pc + y0 * WW + x0);
                float a1 = __ldg(pc + y0 * WW + x1);
                float a2 = __ldg(pc + y1 * WW + x0);
                float a3 = __ldg(pc + y1 * WW + x1);
                float h0 = fmaf(wx, a1 - a0, a0);
                float h1 = fmaf(wx, a3 - a2, a2);
                vv[s] = fmaf(wy, h1 - h0, h0);
            }
            float4 v4 = make_float4(vv[0], vv[1], vv[2], vv[3]);
            *reinterpret_cast<float4*>(oc + (size_t)(ohb + r) * OW + owb) = v4;
        }
    }
}

__global__ void __launch_bounds__(128, 6)
sample_kernel(const float* __restrict__ x, float* __restrict__ out) {
    __shared__ float2 sw[16][128];       // (wx,wy) per output per thread, 16 KB

    int tid = threadIdx.x;
    int t = blockIdx.x * 128 + tid;      // 204800 threads
    int wp = t % 40;  int u = t / 40;
    int hp = u % 40;  u /= 40;
    int cchunk = u & 3;  u >>= 2;
    int gi = u & 3;
    int b  = u >> 2;

    int hbase = 2 * hp, wbase = 2 * wp;

    const float* offb = g_off + (size_t)b * OC * HW;

    bool valid = true;
#pragma unroll
    for (int r = 0; r < 4; r++) {
        int hprime = hbase + (r >> 1);
        int i = r & 1;
#pragma unroll
        for (int s = 0; s < 4; s++) {
            int wprime = wbase + (s >> 1);
            int j = s & 1;
            int k = gi * 4 + i * 2 + j;
            const float* op2 = offb + hprime * WW + wprime;
            float offx = __ldg(op2 + (size_t)k * HW);
            float offy = __ldg(op2 + (size_t)(16 + k) * HW);
            float px = (float)wprime + 0.25f * (offx + (float)(2 * j - 1));
            float py = (float)hprime + 0.25f * (offy + (float)(2 * i - 1));
            float ix = fminf(fmaxf(px, 0.0f), (float)(WW - 1));
            float iy = fminf(fmaxf(py, 0.0f), (float)(HH - 1));
            int tx0 = (s >> 1) + (s & 1);
            int ty0 = (r >> 1) + (r & 1);
            float wx = ix - (float)(wbase - 1 + tx0);
            float wy = iy - (float)(hbase - 1 + ty0);
            sw[r * 4 + s][tid] = make_float2(wx, wy);   // own column: no sync
            valid = valid && (wx >= 0.0f) && (wx <= 1.0f)
                          && (wy >= 0.0f) && (wy <= 1.0f);
        }
    }

    int c0 = cchunk * 16;
    const float* bp = x + (size_t)(b * CH + gi * 64 + c0) * HW;
    int ohb = 4 * hp;
    int owb = 4 * wp;
    float* opb = out + (size_t)(b * CH + gi * 64 + c0) * OHW;

    if (!valid) {
        sample_fallback(offb, bp, opb, gi, hbase, wbase, ohb, owb);
        return;
    }

    int rowo[4];
#pragma unroll
    for (int tq = 0; tq < 4; tq++)
        rowo[tq] = min(max(hbase - 1 + tq, 0), HH - 1) * WW;
    int colL = max(wbase - 1, 0);
    int colR = min(wbase + 2, WW - 1);

#pragma unroll 1
    for (int c = 0; c < 16; c++) {
        const float* pc = bp + (size_t)c * HW;
        float tv[16];
#pragma unroll
        for (int ty = 0; ty < 4; ty++) {
            const float* rowp = pc + rowo[ty];
            tv[ty * 4 + 0] = __ldg(rowp + colL);
            float2 mid = __ldg(reinterpret_cast<const float2*>(rowp + wbase));
            tv[ty * 4 + 1] = mid.x;
            tv[ty * 4 + 2] = mid.y;
            tv[ty * 4 + 3] = __ldg(rowp + colR);
        }

        float* oc = opb + (size_t)c * OHW;
#pragma unroll
        for (int r = 0; r < 4; r++) {
            float vv[4];
#pragma unroll
            for (int s = 0; s < 4; s++) {
                const int tx0 = (s >> 1) + (s & 1);
                const int ty0 = (r >> 1) + (r & 1);
                float a0 = tv[ty0 * 4 + tx0];
                float a1 = tv[ty0 * 4 + tx0 + 1];
                float a2 = tv[(ty0 + 1) * 4 + tx0];
                float a3 = tv[(ty0 + 1) * 4 + tx0 + 1];
                float2 wxy = sw[r * 4 + s][tid];
                float h0 = fmaf(wxy.x, a1 - a0, a0);
                float h1 = fmaf(wxy.x, a3 - a2, a2);
                vv[s] = fmaf(wxy.y, h1 - h0, h0);
            }
            float4 v4 = make_float4(vv[0], vv[1], vv[2], vv[3]);
            *reinterpret_cast<float4*>(oc + (size_t)(ohb + r) * OW + owb) = v4;
        }
    }
}

extern "C" void kernel_launch(void* const* d_in, const int* in_sizes, int n_in,
                              void* d_out, int out_size) {
    const float* x    = (const float*)d_in[0];   // [8,256,80,80]
    const float* wq   = (const float*)d_in[1];   // [32,256,1,1]
    const float* bias = (const float*)d_in[2];   // [32]
    float* out = (float*)d_out;                  // [8,256,160,160]

    pack_w_kernel<<<32, 256>>>(wq);
    conv_off_kernel<<<800, 128>>>(x, bias);
    sample_kernel<<<1600, 128>>>(x, out);
}

// round 10
// speedup vs baseline: 1.1982x; 1.1982x over previous
#include <cuda_runtime.h>
#include <cstdint>

#define BATCH   8
#define CH      256
#define HH      80
#define WW      80
#define HW      (HH*WW)          // 6400
#define HW2     (HW/2)           // 3200 float2 per channel
#define OC      32
#define GROUPS  4
#define OH      160
#define OW      160
#define OHW     (OH*OW)          // 25600

#define QK      64               // channels per K-quarter
#define WPITCH  34               // padded u64 pitch for weight rows (16B aligned, 4-way conflicts)
#define RPITCH  33               // padded u64 pitch for reduction rows
#define SMEM_BYTES (CH * WPITCH * 8)   // 69632 >= reduction region (4*64*33*8 = 67584)

typedef unsigned long long ull;

// scratch for conv output: 8*32*6400 floats = 6.55 MB
__device__ float g_off[BATCH * OC * HW];

__device__ __forceinline__ ull pack2(float a, float b) {
    ull r;
    asm("mov.b64 %0, {%1, %2};" : "=l"(r) : "f"(a), "f"(b));
    return r;
}

__device__ __forceinline__ ull ffma2(ull a, ull b, ull c) {
    ull d;
    asm("fma.rn.f32x2 %0, %1, %2, %3;" : "=l"(d) : "l"(a), "l"(b), "l"(c));
    return d;
}

__device__ __forceinline__ float lo_f(ull v) { return __uint_as_float((unsigned)(v & 0xffffffffULL)); }
__device__ __forceinline__ float hi_f(ull v) { return __uint_as_float((unsigned)(v >> 32)); }

// ---------------------------------------------------------------------------
// Kernel 1 (v10): 1x1 conv, oc-in-registers.
// 400 blocks x 256 thr. Thread = (pair pl = tid&63, K-quarter q = tid>>6):
// one float2 position, ALL 32 oc in 32 u64 accumulators, 64 channels.
// x read once via coalesced LDG.64 (no smem staging, no mainloop barriers).
// Weights packed (w,w) in dyn smem [c][o] pitch 34; inner loop per c:
// 1 LDG.64(x) + 16 bcast LDS.128(w) + 32 FFMA2. Epilogue: 4-way K reduction
// through re-used smem (pitch 33), coalesced float2 stores.
// ---------------------------------------------------------------------------
__global__ void __launch_bounds__(256, 2)
conv_off_kernel(const float* __restrict__ x,
                const float* __restrict__ wq,
                const float* __restrict__ bias) {
    extern __shared__ ull sm[];

    int tid = threadIdx.x;
    // pack weights: sm[c*WPITCH + o] = (w,w). idx -> o = idx>>8 (row), c = idx&255.
    // LDG coalesced over c; STS stride 34*8=272B -> ~4-way conflicts (cheap).
    for (int idx = tid; idx < CH * OC; idx += 256) {
        int o = idx >> 8;
        int c = idx & 255;
        float w = __ldg(&wq[o * CH + c]);
        sm[c * WPITCH + o] = pack2(w, w);
    }
    __syncthreads();

    int pl = tid & 63;                    // pair within block
    int q  = tid >> 6;                    // K-quarter 0..3
    int p  = blockIdx.x * 64 + pl;        // global pair 0..25599
    int b  = p / HW2;
    int pp = p % HW2;

    const ull* xp = reinterpret_cast<const ull*>(x)
                  + (size_t)b * CH * HW2 + (size_t)q * QK * HW2 + pp;
    const ulonglong2* wr0 =
        reinterpret_cast<const ulonglong2*>(sm + q * QK * WPITCH);

    ull acc[32];
#pragma unroll
    for (int o = 0; o < 32; o++) acc[o] = 0ULL;

#pragma unroll 2
    for (int ci = 0; ci < QK; ci++) {
        ull xv = __ldg(xp + (size_t)ci * HW2);
        const ulonglong2* wr = wr0 + ci * (WPITCH / 2);
#pragma unroll
        for (int m = 0; m < 16; m++) {
            ulonglong2 w2 = wr[m];        // broadcast LDS.128 (2 oc)
            acc[2 * m]     = ffma2(xv, w2.x, acc[2 * m]);
            acc[2 * m + 1] = ffma2(xv, w2.y, acc[2 * m + 1]);
        }
    }

    __syncthreads();                      // all weight reads done; re-use sm
    ull* red = sm;                        // [q][pl][o], pitch RPITCH
    {
        ull* myrow = red + (size_t)(q * 64 + pl) * RPITCH;
#pragma unroll
        for (int o = 0; o < 32; o++) myrow[o] = acc[o];
    }
    __syncthreads();

    // thread (pl, q) finalizes oc [8q, 8q+8) for pair pl
    float2* offp = reinterpret_cast<float2*>(g_off) + (size_t)b * OC * HW2 + pp;
#pragma unroll
    for (int oo = 0; oo < 8; oo++) {
        int o = q * 8 + oo;
        ull s0 = red[(size_t)(0 * 64 + pl) * RPITCH + o];
        ull s1 = red[(size_t)(1 * 64 + pl) * RPITCH + o];
        ull s2 = red[(size_t)(2 * 64 + pl) * RPITCH + o];
        ull s3 = red[(size_t)(3 * 64 + pl) * RPITCH + o];
        float bo = __ldg(&bias[o]);
        float lo = ((lo_f(s0) + lo_f(s1)) + (lo_f(s2) + lo_f(s3))) + bo;
        float hi = ((hi_f(s0) + hi_f(s1)) + (hi_f(s2) + hi_f(s3))) + bo;
        offp[(size_t)o * HW2] = make_float2(lo, hi);
    }
}

// ---------------------------------------------------------------------------
// Kernel 2 (v7, unchanged — proven 49.4us): tiled bilinear sampling.
// ---------------------------------------------------------------------------
__device__ __noinline__ void sample_fallback(
    const float* __restrict__ offb, const float* __restrict__ bp,
    float* __restrict__ opb, int gi, int hbase, int wbase, int ohb, int owb)
{
    for (int c = 0; c < 16; c++) {
        const float* pc = bp + (size_t)c * HW;
        float* oc = opb + (size_t)c * OHW;
        for (int r = 0; r < 4; r++) {
            float vv[4];
            for (int s = 0; s < 4; s++) {
                int hprime = hbase + (r >> 1);
                int i = r & 1;
                int wprime = wbase + (s >> 1);
                int j = s & 1;
                int k = gi * 4 + i * 2 + j;
                const float* op2 = offb + hprime * WW + wprime;
                float offx = __ldg(op2 + (size_t)k * HW);
                float offy = __ldg(op2 + (size_t)(16 + k) * HW);
                float px = (float)wprime + 0.25f * (offx + (float)(2 * j - 1));
                float py = (float)hprime + 0.25f * (offy + (float)(2 * i - 1));
                float ix = fminf(fmaxf(px, 0.0f), (float)(WW - 1));
                float iy = fminf(fmaxf(py, 0.0f), (float)(HH - 1));
                float fx = floorf(ix), fy = floorf(iy);
                int x0 = (int)fx, y0 = (int)fy;
                float wx = ix - fx, wy = iy - fy;
                int x1 = min(x0 + 1, WW - 1);
                int y1 = min(y0 + 1, HH - 1);
                float a0 = __ldg(pc + y0 * WW + x0);
                float a1 = __ldg(pc + y0 * WW + x1);
                float a2 = __ldg(pc + y1 * WW + x0);
                float a3 = __ldg(pc + y1 * WW + x1);
                float h0 = fmaf(wx, a1 - a0, a0);
                float h1 = fmaf(wx, a3 - a2, a2);
                vv[s] = fmaf(wy, h1 - h0, h0);
            }
            float4 v4 = make_float4(vv[0], vv[1], vv[2], vv[3]);
            *reinterpret_cast<float4*>(oc + (size_t)(ohb + r) * OW + owb) = v4;
        }
    }
}

__global__ void __launch_bounds__(128, 6)
sample_kernel(const float* __restrict__ x, float* __restrict__ out) {
    __shared__ float2 sw[16][128];       // (wx,wy) per output per thread, 16 KB

    int tid = threadIdx.x;
    int t = blockIdx.x * 128 + tid;      // 204800 threads
    int wp = t % 40;  int u = t / 40;
    int hp = u % 40;  u /= 40;
    int cchunk = u & 3;  u >>= 2;
    int gi = u & 3;
    int b  = u >> 2;

    int hbase = 2 * hp, wbase = 2 * wp;

    const float* offb = g_off + (size_t)b * OC * HW;

    bool valid = true;
#pragma unroll
    for (int r = 0; r < 4; r++) {
        int hprime = hbase + (r >> 1);
        int i = r & 1;
#pragma unroll
        for (int s = 0; s < 4; s++) {
            int wprime = wbase + (s >> 1);
            int j = s & 1;
            int k = gi * 4 + i * 2 + j;
            const float* op2 = offb + hprime * WW + wprime;
            float offx = __ldg(op2 + (size_t)k * HW);
            float offy = __ldg(op2 + (size_t)(16 + k) * HW);
            float px = (float)wprime + 0.25f * (offx + (float)(2 * j - 1));
            float py = (float)hprime + 0.25f * (offy + (float)(2 * i - 1));
            float ix = fminf(fmaxf(px, 0.0f), (float)(WW - 1));
            float iy = fminf(fmaxf(py, 0.0f), (float)(HH - 1));
            int tx0 = (s >> 1) + (s & 1);
            int ty0 = (r >> 1) + (r & 1);
            float wx = ix - (float)(wbase - 1 + tx0);
            float wy = iy - (float)(hbase - 1 + ty0);
            sw[r * 4 + s][tid] = make_float2(wx, wy);   // own column: no sync
            valid = valid && (wx >= 0.0f) && (wx <= 1.0f)
                          && (wy >= 0.0f) && (wy <= 1.0f);
        }
    }

    int c0 = cchunk * 16;
    const float* bp = x + (size_t)(b * CH + gi * 64 + c0) * HW;
    int ohb = 4 * hp;
    int owb = 4 * wp;
    float* opb = out + (size_t)(b * CH + gi * 64 + c0) * OHW;

    if (!valid) {
        sample_fallback(offb, bp, opb, gi, hbase, wbase, ohb, owb);
        return;
    }

    int rowo[4];
#pragma unroll
    for (int tq = 0; tq < 4; tq++)
        rowo[tq] = min(max(hbase - 1 + tq, 0), HH - 1) * WW;
    int colL = max(wbase - 1, 0);
    int colR = min(wbase + 2, WW - 1);

#pragma unroll 1
    for (int c = 0; c < 16; c++) {
        const float* pc = bp + (size_t)c * HW;
        float tv[16];
#pragma unroll
        for (int ty = 0; ty < 4; ty++) {
            const float* rowp = pc + rowo[ty];
            tv[ty * 4 + 0] = __ldg(rowp + colL);
            float2 mid = __ldg(reinterpret_cast<const float2*>(rowp + wbase));
            tv[ty * 4 + 1] = mid.x;
            tv[ty * 4 + 2] = mid.y;
            tv[ty * 4 + 3] = __ldg(rowp + colR);
        }

        float* oc = opb + (size_t)c * OHW;
#pragma unroll
        for (int r = 0; r < 4; r++) {
            float vv[4];
#pragma unroll
            for (int s = 0; s < 4; s++) {
                const int tx0 = (s >> 1) + (s & 1);
                const int ty0 = (r >> 1) + (r & 1);
                float a0 = tv[ty0 * 4 + tx0];
                float a1 = tv[ty0 * 4 + tx0 + 1];
                float a2 = tv[(ty0 + 1) * 4 + tx0];
                float a3 = tv[(ty0 + 1) * 4 + tx0 + 1];
                float2 wxy = sw[r * 4 + s][tid];
                float h0 = fmaf(wxy.x, a1 - a0, a0);
                float h1 = fmaf(wxy.x, a3 - a2, a2);
                vv[s] = fmaf(wxy.y, h1 - h0, h0);
            }
            float4 v4 = make_float4(vv[0], vv[1], vv[2], vv[3]);
            *reinterpret_cast<float4*>(oc + (size_t)(ohb + r) * OW + owb) = v4;
        }
    }
}

extern "C" void kernel_launch(void* const* d_in, const int* in_sizes, int n_in,
                              void* d_out, int out_size) {
    const float* x    = (const float*)d_in[0];   // [8,256,80,80]
    const float* wq   = (const float*)d_in[1];   // [32,256,1,1]
    const float* bias = (const float*)d_in[2];   // [32]
    float* out = (float*)d_out;                  // [8,256,160,160]

    static bool attr_set = false;
    if (!attr_set) {
        cudaFuncSetAttribute(conv_off_kernel,
                             cudaFuncAttributeMaxDynamicSharedMemorySize,
                             SMEM_BYTES);
        attr_set = true;
    }

    conv_off_kernel<<<400, 256, SMEM_BYTES>>>(x, wq, bias);
    sample_kernel<<<1600, 128>>>(x, out);
}

// round 11
// speedup vs baseline: 1.5645x; 1.3057x over previous
#include <cuda_runtime.h>
#include <cstdint>

#define BATCH   8
#define CH      256
#define HH      80
#define WW      80
#define HW      (HH*WW)          // 6400
#define OC      32
#define GROUPS  4
#define OH      160
#define OW      160
#define OHW     (OH*OW)          // 25600

#define SC      16               // channels per conv stage
#define NSTAGE  (CH/SC)          // 16

typedef unsigned long long ull;

// scratch for conv output: 8*32*6400 floats = 6.55 MB
__device__ float g_off[BATCH * OC * HW];

__device__ __forceinline__ ull pack2(float a, float b) {
    ull r;
    asm("mov.b64 %0, {%1, %2};" : "=l"(r) : "f"(a), "f"(b));
    return r;
}

__device__ __forceinline__ ull ffma2(ull a, ull b, ull c) {
    ull d;
    asm("fma.rn.f32x2 %0, %1, %2, %3;" : "=l"(d) : "l"(a), "l"(b), "l"(c));
    return d;
}

// ---------------------------------------------------------------------------
// Kernel 1 (v6 — proven 33.0us, reverted verbatim): 1x1 conv, smem-staged x.
// Block = 256 thr = 8 warps sharing the SAME 32 float4 positions.
// Warp og computes oc [4*og, 4*og+4). x double-buffered (16 ch/stage, 8KB);
// weights unpacked in smem (32KB). Total 48KB static.
// ---------------------------------------------------------------------------
__global__ void __launch_bounds__(256)
conv_off_kernel(const float* __restrict__ x,
                const float* __restrict__ wq,
                const float* __restrict__ bias) {
    __shared__ float  ws[CH * OC];          // [c][o], 32 KB
    __shared__ float4 xs[2][SC][32];        // 2 x 8 KB

    int tid = threadIdx.x;
    for (int idx = tid; idx < CH * OC; idx += 256) {
        int o = idx >> 8;                   // coalesced over c
        int c = idx & 255;
        ws[c * OC + o] = __ldg(&wq[o * CH + c]);
    }

    int b   = blockIdx.x / 50;              // 400 blocks = 8 b x 50
    int qq0 = (blockIdx.x % 50) * 32;       // float4 base within channel
    const float4* xb = reinterpret_cast<const float4*>(x + (size_t)b * CH * HW);

    int c_l0 = tid >> 5;                    // 0..7
    int q0   = tid & 31;

    // prologue: stage 0
    float4 r0 = __ldg(&xb[(size_t)(c_l0)     * (HW / 4) + qq0 + q0]);
    float4 r1 = __ldg(&xb[(size_t)(c_l0 + 8) * (HW / 4) + qq0 + q0]);
    xs[0][c_l0][q0]     = r0;
    xs[0][c_l0 + 8][q0] = r1;
    __syncthreads();                        // covers ws fill + stage 0

    int lane = tid & 31;
    int og   = tid >> 5;                    // 4 oc per warp
    const float* wso = ws + og * 4;

    ull accL[4], accH[4];
#pragma unroll
    for (int o = 0; o < 4; o++) { accL[o] = 0ULL; accH[o] = 0ULL; }

#pragma unroll 1
    for (int st = 0; st < NSTAGE; st++) {
        int cb  = st * SC;
        int buf = st & 1;

        if (st + 1 < NSTAGE) {
            r0 = __ldg(&xb[(size_t)(cb + SC + c_l0)     * (HW / 4) + qq0 + q0]);
            r1 = __ldg(&xb[(size_t)(cb + SC + c_l0 + 8) * (HW / 4) + qq0 + q0]);
        }

#pragma unroll
        for (int cl = 0; cl < SC; cl++) {
            float4 xv = xs[buf][cl][lane];
            ull lo = pack2(xv.x, xv.y);
            ull hi = pack2(xv.z, xv.w);
            float4 w4 = *reinterpret_cast<const float4*>(wso + (cb + cl) * OC);
            ull pw0 = pack2(w4.x, w4.x);
            ull pw1 = pack2(w4.y, w4.y);
            ull pw2 = pack2(w4.z, w4.z);
            ull pw3 = pack2(w4.w, w4.w);
            accL[0] = ffma2(lo, pw0, accL[0]);
            accH[0] = ffma2(hi, pw0, accH[0]);
            accL[1] = ffma2(lo, pw1, accL[1]);
            accH[1] = ffma2(hi, pw1, accH[1]);
            accL[2] = ffma2(lo, pw2, accL[2]);
            accH[2] = ffma2(hi, pw2, accH[2]);
            accL[3] = ffma2(lo, pw3, accL[3]);
            accH[3] = ffma2(hi, pw3, accH[3]);
        }

        __syncthreads();
        if (st + 1 < NSTAGE) {
            xs[buf ^ 1][c_l0][q0]     = r0;
            xs[buf ^ 1][c_l0 + 8][q0] = r1;
            __syncthreads();
        }
    }

    float4* offp = reinterpret_cast<float4*>(g_off + (size_t)b * OC * HW);
#pragma unroll
    for (int o = 0; o < 4; o++) {
        int oc = og * 4 + o;
        float bo = __ldg(&bias[oc]);
        float4 v;
        v.x = __uint_as_float((unsigned)(accL[o] & 0xffffffffULL)) + bo;
        v.y = __uint_as_float((unsigned)(accL[o] >> 32)) + bo;
        v.z = __uint_as_float((unsigned)(accH[o] & 0xffffffffULL)) + bo;
        v.w = __uint_as_float((unsigned)(accH[o] >> 32)) + bo;
        offp[(size_t)oc * (HW / 4) + qq0 + lane] = v;
    }
}

// ---------------------------------------------------------------------------
// Kernel 2 (v8): tiled bilinear sampling; weights packed TWO outputs per
// float4 in smem -> 8 LDS.128 per channel (was 16 LDS.64). Everything else
// identical to the proven v7.
// ---------------------------------------------------------------------------
__device__ __noinline__ void sample_fallback(
    const float* __restrict__ offb, const float* __restrict__ bp,
    float* __restrict__ opb, int gi, int hbase, int wbase, int ohb, int owb)
{
    for (int c = 0; c < 16; c++) {
        const float* pc = bp + (size_t)c * HW;
        float* oc = opb + (size_t)c * OHW;
        for (int r = 0; r < 4; r++) {
            float vv[4];
            for (int s = 0; s < 4; s++) {
                int hprime = hbase + (r >> 1);
                int i = r & 1;
                int wprime = wbase + (s >> 1);
                int j = s & 1;
                int k = gi * 4 + i * 2 + j;
                const float* op2 = offb + hprime * WW + wprime;
                float offx = __ldg(op2 + (size_t)k * HW);
                float offy = __ldg(op2 + (size_t)(16 + k) * HW);
                float px = (float)wprime + 0.25f * (offx + (float)(2 * j - 1));
                float py = (float)hprime + 0.25f * (offy + (float)(2 * i - 1));
                float ix = fminf(fmaxf(px, 0.0f), (float)(WW - 1));
                float iy = fminf(fmaxf(py, 0.0f), (float)(HH - 1));
                float fx = floorf(ix), fy = floorf(iy);
                int x0 = (int)fx, y0 = (int)fy;
                float wx = ix - fx, wy = iy - fy;
                int x1 = min(x0 + 1, WW - 1);
                int y1 = min(y0 + 1, HH - 1);
                float a0 = __ldg(pc + y0 * WW + x0);
                float a1 = __ldg(pc + y0 * WW + x1);
                float a2 = __ldg(pc + y1 * WW + x0);
                float a3 = __ldg(pc + y1 * WW + x1);
                float h0 = fmaf(wx, a1 - a0, a0);
                float h1 = fmaf(wx, a3 - a2, a2);
                vv[s] = fmaf(wy, h1 - h0, h0);
            }
            float4 v4 = make_float4(vv[0], vv[1], vv[2], vv[3]);
            *reinterpret_cast<float4*>(oc + (size_t)(ohb + r) * OW + owb) = v4;
        }
    }
}

__global__ void __launch_bounds__(128, 6)
sample_kernel(const float* __restrict__ x, float* __restrict__ out) {
    // [r*2 + s/2][tid] = (wx_s, wy_s, wx_{s+1}, wy_{s+1}); 16 KB
    __shared__ float4 sw4[8][128];

    int tid = threadIdx.x;
    int t = blockIdx.x * 128 + tid;      // 204800 threads
    int wp = t % 40;  int u = t / 40;
    int hp = u % 40;  u /= 40;
    int cchunk = u & 3;  u >>= 2;
    int gi = u & 3;
    int b  = u >> 2;

    int hbase = 2 * hp, wbase = 2 * wp;

    const float* offb = g_off + (size_t)b * OC * HW;

    bool valid = true;
#pragma unroll
    for (int r = 0; r < 4; r++) {
        int hprime = hbase + (r >> 1);
        int i = r & 1;
#pragma unroll
        for (int s = 0; s < 4; s++) {
            int wprime = wbase + (s >> 1);
            int j = s & 1;
            int k = gi * 4 + i * 2 + j;
            const float* op2 = offb + hprime * WW + wprime;
            float offx = __ldg(op2 + (size_t)k * HW);
            float offy = __ldg(op2 + (size_t)(16 + k) * HW);
            float px = (float)wprime + 0.25f * (offx + (float)(2 * j - 1));
            float py = (float)hprime + 0.25f * (offy + (float)(2 * i - 1));
            float ix = fminf(fmaxf(px, 0.0f), (float)(WW - 1));
            float iy = fminf(fmaxf(py, 0.0f), (float)(HH - 1));
            int tx0 = (s >> 1) + (s & 1);
            int ty0 = (r >> 1) + (r & 1);
            float wx = ix - (float)(wbase - 1 + tx0);
            float wy = iy - (float)(hbase - 1 + ty0);
            // own column, aligned half-write of the float4: no sync needed
            reinterpret_cast<float2*>(&sw4[r * 2 + (s >> 1)][tid])[s & 1] =
                make_float2(wx, wy);
            valid = valid && (wx >= 0.0f) && (wx <= 1.0f)
                          && (wy >= 0.0f) && (wy <= 1.0f);
        }
    }

    int c0 = cchunk * 16;
    const float* bp = x + (size_t)(b * CH + gi * 64 + c0) * HW;
    int ohb = 4 * hp;
    int owb = 4 * wp;
    float* opb = out + (size_t)(b * CH + gi * 64 + c0) * OHW;

    if (!valid) {
        sample_fallback(offb, bp, opb, gi, hbase, wbase, ohb, owb);
        return;
    }

    int rowo[4];
#pragma unroll
    for (int tq = 0; tq < 4; tq++)
        rowo[tq] = min(max(hbase - 1 + tq, 0), HH - 1) * WW;
    int colL = max(wbase - 1, 0);
    int colR = min(wbase + 2, WW - 1);

#pragma unroll 1
    for (int c = 0; c < 16; c++) {
        const float* pc = bp + (size_t)c * HW;
        float tv[16];
#pragma unroll
        for (int ty = 0; ty < 4; ty++) {
            const float* rowp = pc + rowo[ty];
            tv[ty * 4 + 0] = __ldg(rowp + colL);
            float2 mid = __ldg(reinterpret_cast<const float2*>(rowp + wbase));
            tv[ty * 4 + 1] = mid.x;
            tv[ty * 4 + 2] = mid.y;
            tv[ty * 4 + 3] = __ldg(rowp + colR);
        }

        float* oc = opb + (size_t)c * OHW;
#pragma unroll
        for (int r = 0; r < 4; r++) {
            float4 wA = sw4[r * 2 + 0][tid];   // outputs s=0,1
            float4 wB = sw4[r * 2 + 1][tid];   // outputs s=2,3
            float vv[4];
#pragma unroll
            for (int sp = 0; sp < 2; sp++) {
                float4 wp4 = (sp == 0) ? wA : wB;
#pragma unroll
                for (int e = 0; e < 2; e++) {
                    int s = sp * 2 + e;
                    const int tx0 = (s >> 1) + (s & 1);
                    const int ty0 = (r >> 1) + (r & 1);
                    float wx = e ? wp4.z : wp4.x;
                    float wy = e ? wp4.w : wp4.y;
                    float a0 = tv[ty0 * 4 + tx0];
                    float a1 = tv[ty0 * 4 + tx0 + 1];
                    float a2 = tv[(ty0 + 1) * 4 + tx0];
                    float a3 = tv[(ty0 + 1) * 4 + tx0 + 1];
                    float h0 = fmaf(wx, a1 - a0, a0);
                    float h1 = fmaf(wx, a3 - a2, a2);
                    vv[s] = fmaf(wy, h1 - h0, h0);
                }
            }
            float4 v4 = make_float4(vv[0], vv[1], vv[2], vv[3]);
            *reinterpret_cast<float4*>(oc + (size_t)(ohb + r) * OW + owb) = v4;
        }
    }
}

extern "C" void kernel_launch(void* const* d_in, const int* in_sizes, int n_in,
                              void* d_out, int out_size) {
    const float* x    = (const float*)d_in[0];   // [8,256,80,80]
    const float* wq   = (const float*)d_in[1];   // [32,256,1,1]
    const float* bias = (const float*)d_in[2];   // [32]
    float* out = (float*)d_out;                  // [8,256,160,160]

    conv_off_kernel<<<400, 256>>>(x, wq, bias);
    sample_kernel<<<1600, 128>>>(x, out);
}